// round 1
// baseline (speedup 1.0000x reference)
#include <cuda_runtime.h>
#include <math.h>

// ---------------------------------------------------------------------------
// Problem constants
// ---------------------------------------------------------------------------
#define BW        32768     // B*W
#define LW        3         // L
#define NODE_DIM  172
#define EDGE_DIM  172
#define TIME_DIM  172
#define EVT_K     347       // EDGE_DIM + 3 + TIME_DIM
#define HID       64

#define PAIRS     16        // (b,w) pairs per block
#define ROWS      (PAIRS*LW)   // 48
#define NBLK      (BW/PAIRS)   // 2048
#define NTHREADS  256

// SMEM layout (floats)
#define EF_STRIDE   352          // event_f row stride (K padded 347->352)
#define EF_OFF      0            // 48*352 = 16896
#define EVT_OFF     16896        // event 48x176 = 8448
#define IN_OFF      25344        // in    48x176 = 8448
#define WS_OFF      33792        // weight staging, 16384 floats (64KB)
#define FEAT_OFF    50176        // feat 48x128 = 6144
#define SMEM_FLOATS 56320
#define SMEM_BYTES  (SMEM_FLOATS*4)   // 225280 B

// aliases inside EF region (valid after gine phase: src/tgt dead)
#define WP_OFF      (EF_OFF + 0)        // 16x128
#define WQ_OFF      (EF_OFF + 2048)     // 32x128
#define TGTB_OFF    (EF_OFF + 6144)     // 32x128
#define OUTB_OFF    (EF_OFF + 10240)    // 16x128
#define HB_OFF      (EF_OFF + 12288)    // 16x64
#define SF_OFF      (EF_OFF + 13312)    // 16x64
#define XB_OFF      (EF_OFF + 14336)    // 16x76
// aliases inside EVT region for the MLP tail
#define SC_OFF      (EVT_OFF + 0)       // 32 scores/alphas
#define H1_OFF      (EVT_OFF + 64)      // 16x76
#define H2_OFF      (EVT_OFF + 64 + 16*76) // 16x64

// h (gine hidden) lives inside the top of the Ws region (gcn staging uses <=11264)
#define H_OFF       (WS_OFF + 11264)    // 48x64 = 3072

// ---------------------------------------------------------------------------
// Pre-transposed / padded weights in device scratch
// ---------------------------------------------------------------------------
__device__ __align__(16) float g_WT_event[348*192];  // [k][o], zero padded
__device__ __align__(16) float g_WT_gcn1 [176*64];
__device__ __align__(16) float g_WT_gcn2 [ 64*64];
__device__ __align__(16) float g_WT_att1 [128*128];
__device__ __align__(16) float g_WT_att2 [128*128];
__device__ __align__(16) float g_WT_m1   [128*64];
__device__ __align__(16) float g_WT_m2   [ 64*64];

__global__ void prep_kernel(const float* __restrict__ ew,
                            const float* __restrict__ g1,
                            const float* __restrict__ g2,
                            const float* __restrict__ a1,
                            const float* __restrict__ a2,
                            const float* __restrict__ m1,
                            const float* __restrict__ m2)
{
    int t0 = blockIdx.x*blockDim.x + threadIdx.x;
    int stride = gridDim.x*blockDim.x;
    for (int i = t0; i < 348*192; i += stride) {
        int k = i/192, o = i%192;
        g_WT_event[i] = (k < 347 && o < 172) ? ew[o*347 + k] : 0.f;
    }
    for (int i = t0; i < 176*64; i += stride) {
        int k = i/64, o = i%64;
        g_WT_gcn1[i] = (k < 172) ? g1[o*172 + k] : 0.f;
    }
    for (int i = t0; i < 64*64; i += stride) {
        int k = i/64, o = i%64;
        g_WT_gcn2[i] = g2[o*64 + k];
        g_WT_m2[i]   = m2[o*64 + k];
    }
    for (int i = t0; i < 128*128; i += stride) {
        int k = i/128, o = i%128;
        g_WT_att1[i] = a1[o*128 + k];
        g_WT_att2[i] = a2[o*128 + k];
    }
    for (int i = t0; i < 128*64; i += stride) {
        int k = i/64, o = i%64;
        g_WT_m1[i] = m1[o*128 + k];
    }
}

// ---------------------------------------------------------------------------
// Generic SMEM-staged register-tiled GEMM:
//   C[M][N(real NREAL)] = op( A[M][K] @ WT[K][N] + bias )
// Thread grid fixed 16x16 (256 threads). RT=M/16 rows, CT=N/16 cols per thread.
// ---------------------------------------------------------------------------
template<int M, int N, int K, int KC, int RT, int CT, bool RELU, int NREAL>
__device__ __forceinline__ void gemm_tile(
    const float* __restrict__ WT,       // global, [K][N] padded
    const float* __restrict__ bias,     // global, NREAL
    const float* __restrict__ A, int sa,// smem, row pitch sa
    float* __restrict__ C, int sc,      // smem, row pitch sc
    float* __restrict__ Ws, int tid)
{
    static_assert(M == 16*RT && N == 16*CT && (CT % 4) == 0 && (K % KC) == 0, "tiling");
    const int ty = tid >> 4, tx = tid & 15;

    float acc[RT][CT];
#pragma unroll
    for (int i = 0; i < RT; i++)
#pragma unroll
        for (int j = 0; j < CT; j++) acc[i][j] = 0.f;

#pragma unroll 1
    for (int kc = 0; kc < K; kc += KC) {
        // stage weight chunk (coalesced float4)
        const float4* srcv = reinterpret_cast<const float4*>(WT + kc*N);
        float4* dstv = reinterpret_cast<float4*>(Ws);
        for (int i = tid; i < (KC*N)/4; i += NTHREADS) dstv[i] = srcv[i];
        __syncthreads();

#pragma unroll 2
        for (int k = 0; k < KC; k++) {
            float a[RT];
#pragma unroll
            for (int i = 0; i < RT; i++) a[i] = A[(ty*RT + i)*sa + kc + k];
            const float* wrow = Ws + k*N + tx*CT;
#pragma unroll
            for (int j4 = 0; j4 < CT/4; j4++) {
                float4 w = *reinterpret_cast<const float4*>(wrow + 4*j4);
#pragma unroll
                for (int i = 0; i < RT; i++) {
                    acc[i][4*j4+0] += a[i]*w.x;
                    acc[i][4*j4+1] += a[i]*w.y;
                    acc[i][4*j4+2] += a[i]*w.z;
                    acc[i][4*j4+3] += a[i]*w.w;
                }
            }
        }
        __syncthreads();
    }

#pragma unroll
    for (int i = 0; i < RT; i++)
#pragma unroll
        for (int j = 0; j < CT; j++) {
            int c = tx*CT + j;
            if (c < NREAL) {
                float v = acc[i][j] + bias[c];
                if (RELU) v = fmaxf(v, 0.f);
                C[(ty*RT + i)*sc + c] = v;
            }
        }
    __syncthreads();
}

// ---------------------------------------------------------------------------
// Fused main kernel: one block handles 16 (b,w) pairs end-to-end.
// ---------------------------------------------------------------------------
__global__ void __launch_bounds__(NTHREADS, 1)
fused_kernel(const int*   __restrict__ node_idx,     // BW x 6
             const int*   __restrict__ edge_idx,     // BW x 3
             const int*   __restrict__ cat_feat,     // BW
             const float* __restrict__ t_records,    // BW x 3
             const float* __restrict__ edge_identify,// BW x 3 x 3
             const float* __restrict__ node_embed,   // 10000 x 172
             const float* __restrict__ edge_embed,   // 200000 x 172
             const float* __restrict__ basis_freq,   // 172
             const float* __restrict__ phase,        // 172
             const float* __restrict__ lin_event_b,  // 172
             const float* __restrict__ gcn_b1,       // 64
             const float* __restrict__ gcn_b2,       // 64
             const float* __restrict__ att_w1_b,     // 128
             const float* __restrict__ att_w2_b,     // 128
             const float* __restrict__ att_m1_b,     // 64
             const float* __restrict__ att_m2_b,     // 64
             const float* __restrict__ mlp_w1,       // 76x76
             const float* __restrict__ mlp_b1,       // 76
             const float* __restrict__ mlp_w2,       // 64x76
             const float* __restrict__ mlp_b2,       // 64
             const float* __restrict__ mlp_w3,       // 1x64
             const float* __restrict__ mlp_b3,       // 1
             float*       __restrict__ out)          // BW
{
    extern __shared__ float sm[];
    const int tid = threadIdx.x;
    const int g0  = blockIdx.x * PAIRS;

    float* ef   = sm + EF_OFF;
    float* evt  = sm + EVT_OFF;
    float* inb  = sm + IN_OFF;
    float* Ws   = sm + WS_OFF;
    float* feat = sm + FEAT_OFF;
    float* hbuf = sm + H_OFF;

    // ---------------- Phase 1: build event_f [48][352] ----------------
    for (int idx = tid; idx < ROWS*EF_STRIDE; idx += NTHREADS) {
        int r = idx / EF_STRIDE, c = idx % EF_STRIDE;
        int p = r / 3, l = r % 3;
        int g = g0 + p;
        float v = 0.f;
        if (c < 172) {
            int e = edge_idx[g*3 + l];
            v = edge_embed[(long)e*172 + c];
        } else if (c < 175) {
            v = edge_identify[(g*3 + l)*3 + (c - 172)];
        } else if (c < 347) {
            int d = c - 175;
            float dt = t_records[g*3 + 2] - t_records[g*3 + l];
            v = cosf(dt * basis_freq[d] + phase[d]);
        }
        ef[idx] = v;
    }
    // event = event_f @ lin_event_w^T + b   -> evt [48][176] (cols<172 valid)
    gemm_tile<48,192,348,58,3,12,false,172>(g_WT_event, lin_event_b, ef, EF_STRIDE,
                                            evt, 176, Ws, tid);

    // ---------------- Phase 2: gathers src/tgt [48][176] ----------------
    float* srcf = ef;           // reuse event_f region
    float* tgtf = ef + 8448;
    for (int idx = tid; idx < ROWS*176; idx += NTHREADS) {
        int r = idx / 176, c = idx % 176;
        int p = r / 3, l = r % 3;
        int g = g0 + p;
        float s = 0.f, t = 0.f;
        if (c < 172) {
            int ns = node_idx[g*6 + 2*l];
            int nt = node_idx[g*6 + 2*l + 1];
            s = node_embed[(long)ns*172 + c];
            t = node_embed[(long)nt*172 + c];
        }
        srcf[idx] = s;
        tgtf[idx] = t;
    }
    __syncthreads();

    // ---------------- Phase 3: gine(src, tgt) -> feat[:, 0:64] ----------------
    for (int idx = tid; idx < ROWS*176; idx += NTHREADS) {
        int c = idx % 176;
        float v = 0.f;
        if (c < 172) v = srcf[idx] + fmaxf(tgtf[idx] + evt[idx], 0.f);
        inb[idx] = v;
    }
    __syncthreads();
    gemm_tile<48,64,176,176,3,4,true,64>(g_WT_gcn1, gcn_b1, inb, 176, hbuf, 64, Ws, tid);
    gemm_tile<48,64,64,64,3,4,false,64>(g_WT_gcn2, gcn_b2, hbuf, 64, feat + 0, 128, Ws, tid);

    // ---------------- Phase 4: gine(tgt, src) -> feat[:, 64:128] ----------------
    for (int idx = tid; idx < ROWS*176; idx += NTHREADS) {
        int c = idx % 176;
        float v = 0.f;
        if (c < 172) v = tgtf[idx] + fmaxf(srcf[idx] + evt[idx], 0.f);
        inb[idx] = v;
    }
    __syncthreads();
    gemm_tile<48,64,176,176,3,4,true,64>(g_WT_gcn1, gcn_b1, inb, 176, hbuf, 64, Ws, tid);
    gemm_tile<48,64,64,64,3,4,false,64>(g_WT_gcn2, gcn_b2, hbuf, 64, feat + 64, 128, Ws, tid);
    // src/tgt/evt/in now dead; EF & EVT regions reusable.

    // ---------------- Phase 5: attention ----------------
    float* Wp   = sm + WP_OFF;
    float* Wq   = sm + WQ_OFF;
    float* tgtb = sm + TGTB_OFF;
    float* outb = sm + OUTB_OFF;
    float* scb  = sm + SC_OFF;

    // gather tgt rows: row r (0..31) -> feat row (r/2)*3 + (r%2)
    for (int idx = tid; idx < 32*128; idx += NTHREADS) {
        int r = idx / 128, c = idx % 128;
        tgtb[idx] = feat[((r >> 1)*3 + (r & 1))*128 + c];
    }
    // Wp = src @ att_w1^T + b   (src rows = feat rows 3p+2, pitch 384)
    gemm_tile<16,128,128,128,1,8,false,128>(g_WT_att1, att_w1_b,
                                            feat + 2*128, 384, Wp, 128, Ws, tid);
    // Wq = tgt @ att_w2^T + b
    gemm_tile<32,128,128,128,2,8,false,128>(g_WT_att2, att_w2_b,
                                            tgtb, 128, Wq, 128, Ws, tid);

    // scores[p][k] = dot(Wp[p], Wq[2p+k]);  8 lanes per (p,k)
    {
        int pk = tid >> 3, sub = tid & 7;   // pk 0..31
        int p = pk >> 1, k = pk & 1;
        float s = 0.f;
        for (int j = sub; j < 128; j += 8)
            s += Wp[p*128 + j] * Wq[(2*p + k)*128 + j];
        s += __shfl_down_sync(0xffffffffu, s, 4, 8);
        s += __shfl_down_sync(0xffffffffu, s, 2, 8);
        s += __shfl_down_sync(0xffffffffu, s, 1, 8);
        if (sub == 0) scb[pk] = s;
    }
    __syncthreads();
    if (tid < 16) {
        float s0 = scb[2*tid], s1 = scb[2*tid + 1];
        float m = fmaxf(s0, s1);
        float e0 = expf(s0 - m), e1 = expf(s1 - m);
        float inv = 1.f / (e0 + e1);
        scb[2*tid]     = e0 * inv;
        scb[2*tid + 1] = e1 * inv;
    }
    __syncthreads();
    // out = src + a0*Wq0 + a1*Wq1
    for (int idx = tid; idx < 16*128; idx += NTHREADS) {
        int p = idx / 128, c = idx % 128;
        outb[idx] = feat[(p*3 + 2)*128 + c]
                  + scb[2*p]     * Wq[(2*p)*128 + c]
                  + scb[2*p + 1] * Wq[(2*p + 1)*128 + c];
    }
    __syncthreads();

    float* hb = sm + HB_OFF;
    float* sf = sm + SF_OFF;
    gemm_tile<16,64,128,128,1,4,true,64>(g_WT_m1, att_m1_b, outb, 128, hb, 64, Ws, tid);
    gemm_tile<16,64,64,64,1,4,false,64>(g_WT_m2, att_m2_b, hb, 64, sf, 64, Ws, tid);

    // ---------------- Phase 6: MLP tail ----------------
    float* xb  = sm + XB_OFF;   // 16x76
    float* h1b = sm + H1_OFF;   // 16x76
    float* h2b = sm + H2_OFF;   // 16x64
    for (int idx = tid; idx < 16*76; idx += NTHREADS) {
        int p = idx / 76, c = idx % 76;
        float v;
        if (c < 64) v = sf[p*64 + c];
        else        v = (cat_feat[g0 + p] == (c - 64)) ? 1.f : 0.f;
        xb[idx] = v;
    }
    __syncthreads();
    for (int idx = tid; idx < 16*76; idx += NTHREADS) {
        int p = idx / 76, c = idx % 76;
        const float* w = mlp_w1 + c*76;
        const float* x = xb + p*76;
        float s = mlp_b1[c];
#pragma unroll 4
        for (int k = 0; k < 76; k++) s += x[k] * w[k];
        h1b[idx] = fmaxf(s, 0.f);
    }
    __syncthreads();
    for (int idx = tid; idx < 16*64; idx += NTHREADS) {
        int p = idx / 64, c = idx % 64;
        const float* w = mlp_w2 + c*76;
        const float* x = h1b + p*76;
        float s = mlp_b2[c];
#pragma unroll 4
        for (int k = 0; k < 76; k++) s += x[k] * w[k];
        h2b[idx] = fmaxf(s, 0.f);
    }
    __syncthreads();
    if (tid < 16) {
        float z = mlp_b3[0];
        const float* x = h2b + tid*64;
#pragma unroll 4
        for (int k = 0; k < 64; k++) z += x[k] * mlp_w3[k];
        out[g0 + tid] = 1.f / (1.f + expf(-z));
    }
}

// ---------------------------------------------------------------------------
// Launch
// ---------------------------------------------------------------------------
extern "C" void kernel_launch(void* const* d_in, const int* in_sizes, int n_in,
                              void* d_out, int out_size)
{
    const int*   node_idx      = (const int*)  d_in[0];
    const int*   edge_idx      = (const int*)  d_in[1];
    const int*   cat_feat      = (const int*)  d_in[2];
    const float* t_records     = (const float*)d_in[3];
    const float* edge_identify = (const float*)d_in[4];
    // d_in[5] = cut_time_l (unused by reference)
    const float* node_embed    = (const float*)d_in[6];
    const float* edge_embed    = (const float*)d_in[7];
    const float* basis_freq    = (const float*)d_in[8];
    const float* phase         = (const float*)d_in[9];
    const float* lin_event_w   = (const float*)d_in[10];
    const float* lin_event_b   = (const float*)d_in[11];
    const float* gcn_w1        = (const float*)d_in[12];
    const float* gcn_b1        = (const float*)d_in[13];
    const float* gcn_w2        = (const float*)d_in[14];
    const float* gcn_b2        = (const float*)d_in[15];
    const float* att_w1_w      = (const float*)d_in[16];
    const float* att_w1_b      = (const float*)d_in[17];
    const float* att_w2_w      = (const float*)d_in[18];
    const float* att_w2_b      = (const float*)d_in[19];
    const float* att_m1_w      = (const float*)d_in[20];
    const float* att_m1_b      = (const float*)d_in[21];
    const float* att_m2_w      = (const float*)d_in[22];
    const float* att_m2_b      = (const float*)d_in[23];
    const float* mlp_w1        = (const float*)d_in[24];
    const float* mlp_b1        = (const float*)d_in[25];
    const float* mlp_w2        = (const float*)d_in[26];
    const float* mlp_b2        = (const float*)d_in[27];
    const float* mlp_w3        = (const float*)d_in[28];
    const float* mlp_b3        = (const float*)d_in[29];
    float* outp = (float*)d_out;

    cudaFuncSetAttribute(fused_kernel,
                         cudaFuncAttributeMaxDynamicSharedMemorySize, SMEM_BYTES);

    prep_kernel<<<128, 256>>>(lin_event_w, gcn_w1, gcn_w2,
                              att_w1_w, att_w2_w, att_m1_w, att_m2_w);

    fused_kernel<<<NBLK, NTHREADS, SMEM_BYTES>>>(
        node_idx, edge_idx, cat_feat, t_records, edge_identify,
        node_embed, edge_embed, basis_freq, phase,
        lin_event_b, gcn_b1, gcn_b2,
        att_w1_b, att_w2_b, att_m1_b, att_m2_b,
        mlp_w1, mlp_b1, mlp_w2, mlp_b2, mlp_w3, mlp_b3,
        outp);
}

// round 2
// speedup vs baseline: 1.2499x; 1.2499x over previous
#include <cuda_runtime.h>
#include <math.h>

// ---------------------------------------------------------------------------
// Problem constants
// ---------------------------------------------------------------------------
#define BW        32768     // B*W
#define PAIRS     16        // (b,w) pairs per block
#define ROWS      48        // PAIRS*3
#define NBLK      (BW/PAIRS)   // 2048
#define NTHREADS  256

// SMEM layout (floats). Total 28672 floats = 114688 B -> 2 blocks/SM.
#define EVT_OFF     0            // 48x176 = 8448
#define INB_OFF     8448         // 48x176 = 8448
#define WS_OFF      16896        // 5632 floats (22KB weight staging)
#define FEAT_OFF    22528        // 48x128 = 6144
#define SMEM_FLOATS 28672
#define SMEM_BYTES  (SMEM_FLOATS*4)

// aliases (regions reused across phases)
#define WP_OFF      (EVT_OFF + 0)       // 16x128
#define WQ_OFF      (EVT_OFF + 2048)    // 32x128
#define SC_OFF      (EVT_OFF + 6144)    // 32
#define TGTB_OFF    (INB_OFF + 0)       // 32x128
#define OUTB_OFF    (INB_OFF + 4096)    // 16x128
#define HB_OFF      (INB_OFF + 6144)    // 16x64
#define SF_OFF      (INB_OFF + 7168)    // 16x64
#define XB_OFF      (INB_OFF + 0)       // 16x76 (tgtb dead by then)
#define H1_OFF      (INB_OFF + 1280)    // 16x76
#define H2_OFF      (INB_OFF + 2560)    // 16x64

// ---------------------------------------------------------------------------
// Pre-transposed / padded weights in device scratch
// ---------------------------------------------------------------------------
__device__ __align__(16) float g_WT_event[348*192];  // [k][o], zero padded
__device__ __align__(16) float g_WT_gcn1 [176*64];
__device__ __align__(16) float g_WT_gcn2 [ 64*64];
__device__ __align__(16) float g_WT_att1 [128*128];
__device__ __align__(16) float g_WT_att2 [128*128];
__device__ __align__(16) float g_WT_m1   [128*64];
__device__ __align__(16) float g_WT_m2   [ 64*64];

__global__ void prep_kernel(const float* __restrict__ ew,
                            const float* __restrict__ g1,
                            const float* __restrict__ g2,
                            const float* __restrict__ a1,
                            const float* __restrict__ a2,
                            const float* __restrict__ m1,
                            const float* __restrict__ m2)
{
    int t0 = blockIdx.x*blockDim.x + threadIdx.x;
    int stride = gridDim.x*blockDim.x;
    for (int i = t0; i < 348*192; i += stride) {
        int k = i/192, o = i%192;
        g_WT_event[i] = (k < 347 && o < 172) ? ew[o*347 + k] : 0.f;
    }
    for (int i = t0; i < 176*64; i += stride) {
        int k = i/64, o = i%64;
        g_WT_gcn1[i] = (k < 172) ? g1[o*172 + k] : 0.f;
    }
    for (int i = t0; i < 64*64; i += stride) {
        int k = i/64, o = i%64;
        g_WT_gcn2[i] = g2[o*64 + k];
        g_WT_m2[i]   = m2[o*64 + k];
    }
    for (int i = t0; i < 128*128; i += stride) {
        int k = i/128, o = i%128;
        g_WT_att1[i] = a1[o*128 + k];
        g_WT_att2[i] = a2[o*128 + k];
    }
    for (int i = t0; i < 128*64; i += stride) {
        int k = i/64, o = i%64;
        g_WT_m1[i] = m1[o*128 + k];
    }
}

// ---------------------------------------------------------------------------
// Generic SMEM-staged register-tiled GEMM (16x16 thread grid)
//   C[M][NREAL] = op( A[M][K] @ WT[K][N] + bias )
// ---------------------------------------------------------------------------
template<int M, int N, int K, int KC, int RT, int CT, bool RELU, int NREAL>
__device__ __forceinline__ void gemm_tile(
    const float* __restrict__ WT,
    const float* __restrict__ bias,
    const float* __restrict__ A, int sa,
    float* __restrict__ C, int sc,
    float* __restrict__ Ws, int tid)
{
    static_assert(M == 16*RT && N == 16*CT && (CT % 4) == 0 && (K % KC) == 0, "tiling");
    const int ty = tid >> 4, tx = tid & 15;

    float acc[RT][CT];
#pragma unroll
    for (int i = 0; i < RT; i++)
#pragma unroll
        for (int j = 0; j < CT; j++) acc[i][j] = 0.f;

#pragma unroll 1
    for (int kc = 0; kc < K; kc += KC) {
        const float4* srcv = reinterpret_cast<const float4*>(WT + kc*N);
        float4* dstv = reinterpret_cast<float4*>(Ws);
        for (int i = tid; i < (KC*N)/4; i += NTHREADS) dstv[i] = srcv[i];
        __syncthreads();

#pragma unroll 2
        for (int k = 0; k < KC; k++) {
            float a[RT];
#pragma unroll
            for (int i = 0; i < RT; i++) a[i] = A[(ty*RT + i)*sa + kc + k];
            const float* wrow = Ws + k*N + tx*CT;
#pragma unroll
            for (int j4 = 0; j4 < CT/4; j4++) {
                float4 w = *reinterpret_cast<const float4*>(wrow + 4*j4);
#pragma unroll
                for (int i = 0; i < RT; i++) {
                    acc[i][4*j4+0] += a[i]*w.x;
                    acc[i][4*j4+1] += a[i]*w.y;
                    acc[i][4*j4+2] += a[i]*w.z;
                    acc[i][4*j4+3] += a[i]*w.w;
                }
            }
        }
        __syncthreads();
    }

#pragma unroll
    for (int i = 0; i < RT; i++)
#pragma unroll
        for (int j = 0; j < CT; j++) {
            int c = tx*CT + j;
            if (c < NREAL) {
                float v = acc[i][j] + bias[c];
                if (RELU) v = fmaxf(v, 0.f);
                C[(ty*RT + i)*sc + c] = v;
            }
        }
    __syncthreads();
}

// ---------------------------------------------------------------------------
// Fused main kernel: one block handles 16 (b,w) pairs end-to-end.
// ---------------------------------------------------------------------------
__global__ void __launch_bounds__(NTHREADS, 2)
fused_kernel(const int*   __restrict__ node_idx,     // BW x 6
             const int*   __restrict__ edge_idx,     // BW x 3
             const int*   __restrict__ cat_feat,     // BW
             const float* __restrict__ t_records,    // BW x 3
             const float* __restrict__ edge_identify,// BW x 3 x 3
             const float* __restrict__ node_embed,   // 10000 x 172
             const float* __restrict__ edge_embed,   // 200000 x 172
             const float* __restrict__ basis_freq,   // 172
             const float* __restrict__ phase,        // 172
             const float* __restrict__ lin_event_b,  // 172
             const float* __restrict__ gcn_b1,
             const float* __restrict__ gcn_b2,
             const float* __restrict__ att_w1_b,
             const float* __restrict__ att_w2_b,
             const float* __restrict__ att_m1_b,
             const float* __restrict__ att_m2_b,
             const float* __restrict__ mlp_w1,
             const float* __restrict__ mlp_b1,
             const float* __restrict__ mlp_w2,
             const float* __restrict__ mlp_b2,
             const float* __restrict__ mlp_w3,
             const float* __restrict__ mlp_b3,
             float*       __restrict__ out)
{
    extern __shared__ float sm[];
    const int tid = threadIdx.x;
    const int ty = tid >> 4, tx = tid & 15;
    const int g0  = blockIdx.x * PAIRS;

    float* evt  = sm + EVT_OFF;
    float* inb  = sm + INB_OFF;
    float* Ws   = sm + WS_OFF;
    float* feat = sm + FEAT_OFF;

    // ============ Phase 1: event linear with on-the-fly A generation ========
    // event_f cols: [0,172) edge_embed gather, [172,175) identify,
    //               [175,347) cos(dt*freq+phase), 347 pad.
    {
        float* Abuf = inb;       // 48 x 29, pitch 29
        float acc[3][12];
#pragma unroll
        for (int i = 0; i < 3; i++)
#pragma unroll
            for (int j = 0; j < 12; j++) acc[i][j] = 0.f;

#pragma unroll 1
        for (int kc = 0; kc < 348; kc += 29) {
            __syncthreads();   // protect Abuf/Ws vs previous chunk's reads
            // generate A chunk
            for (int idx = tid; idx < ROWS*29; idx += NTHREADS) {
                int r = idx / 29, cc = idx % 29;
                int c = kc + cc;
                int p = r / 3, l = r % 3;
                int g = g0 + p;
                float v = 0.f;
                if (c < 172) {
                    int e = __ldg(&edge_idx[g*3 + l]);
                    v = __ldg(&edge_embed[(long)e*172 + c]);
                } else if (c < 175) {
                    v = __ldg(&edge_identify[(g*3 + l)*3 + (c - 172)]);
                } else if (c < 347) {
                    int d = c - 175;
                    float dt = __ldg(&t_records[g*3 + 2]) - __ldg(&t_records[g*3 + l]);
                    v = __cosf(dt * __ldg(&basis_freq[d]) + __ldg(&phase[d]));
                }
                Abuf[idx] = v;
            }
            // stage weight chunk 29x192
            {
                const float4* srcv = reinterpret_cast<const float4*>(g_WT_event + kc*192);
                float4* dstv = reinterpret_cast<float4*>(Ws);
                for (int i = tid; i < (29*192)/4; i += NTHREADS) dstv[i] = srcv[i];
            }
            __syncthreads();
#pragma unroll 2
            for (int k = 0; k < 29; k++) {
                float a[3];
#pragma unroll
                for (int i = 0; i < 3; i++) a[i] = Abuf[(ty*3 + i)*29 + k];
                const float* wrow = Ws + k*192 + tx*12;
#pragma unroll
                for (int j4 = 0; j4 < 3; j4++) {
                    float4 w = *reinterpret_cast<const float4*>(wrow + 4*j4);
#pragma unroll
                    for (int i = 0; i < 3; i++) {
                        acc[i][4*j4+0] += a[i]*w.x;
                        acc[i][4*j4+1] += a[i]*w.y;
                        acc[i][4*j4+2] += a[i]*w.z;
                        acc[i][4*j4+3] += a[i]*w.w;
                    }
                }
            }
        }
        __syncthreads();
#pragma unroll
        for (int i = 0; i < 3; i++)
#pragma unroll
            for (int j = 0; j < 12; j++) {
                int c = tx*12 + j;
                if (c < 172) evt[(ty*3 + i)*176 + c] = acc[i][j] + lin_event_b[c];
            }
        __syncthreads();
    }

    // ============ Phase 2: gine(src, tgt) -> feat[:, 0:64] ==================
    for (int idx = tid; idx < ROWS*176; idx += NTHREADS) {
        int r = idx / 176, c = idx % 176;
        int p = r / 3, l = r % 3;
        int g = g0 + p;
        float v = 0.f;
        if (c < 172) {
            int ns = __ldg(&node_idx[g*6 + 2*l]);
            int nt = __ldg(&node_idx[g*6 + 2*l + 1]);
            float s = __ldg(&node_embed[(long)ns*172 + c]);
            float t = __ldg(&node_embed[(long)nt*172 + c]);
            v = s + fmaxf(t + evt[idx], 0.f);
        }
        inb[idx] = v;
    }
    __syncthreads();
    // H (gine hidden) lives in feat[:,64:128] for pass 1
    gemm_tile<48,64,176,88,3,4,true,64>(g_WT_gcn1, gcn_b1, inb, 176, feat + 64, 128, Ws, tid);
    gemm_tile<48,64,64,64,3,4,false,64>(g_WT_gcn2, gcn_b2, feat + 64, 128, feat + 0, 128, Ws, tid);

    // ============ Phase 3: gine(tgt, src) -> feat[:, 64:128] ================
    for (int idx = tid; idx < ROWS*176; idx += NTHREADS) {
        int r = idx / 176, c = idx % 176;
        int p = r / 3, l = r % 3;
        int g = g0 + p;
        float v = 0.f;
        if (c < 172) {
            int ns = __ldg(&node_idx[g*6 + 2*l]);
            int nt = __ldg(&node_idx[g*6 + 2*l + 1]);
            float s = __ldg(&node_embed[(long)ns*172 + c]);
            float t = __ldg(&node_embed[(long)nt*172 + c]);
            v = t + fmaxf(s + evt[idx], 0.f);
        }
        inb[idx] = v;
    }
    __syncthreads();
    // evt is dead now: H lives in evt region for pass 2
    gemm_tile<48,64,176,88,3,4,true,64>(g_WT_gcn1, gcn_b1, inb, 176, evt, 64, Ws, tid);
    gemm_tile<48,64,64,64,3,4,false,64>(g_WT_gcn2, gcn_b2, evt, 64, feat + 64, 128, Ws, tid);

    // ============ Phase 4: attention =========================================
    float* Wp   = sm + WP_OFF;
    float* Wq   = sm + WQ_OFF;
    float* tgtb = sm + TGTB_OFF;
    float* outb = sm + OUTB_OFF;
    float* scb  = sm + SC_OFF;

    // gather tgt rows: row r (0..31) -> feat row (r/2)*3 + (r%2)
    for (int idx = tid; idx < 32*128; idx += NTHREADS) {
        int r = idx / 128, c = idx % 128;
        tgtb[idx] = feat[((r >> 1)*3 + (r & 1))*128 + c];
    }
    __syncthreads();
    gemm_tile<16,128,128,32,1,8,false,128>(g_WT_att1, att_w1_b,
                                           feat + 2*128, 384, Wp, 128, Ws, tid);
    gemm_tile<32,128,128,32,2,8,false,128>(g_WT_att2, att_w2_b,
                                           tgtb, 128, Wq, 128, Ws, tid);

    // scores[p][k] = dot(Wp[p], Wq[2p+k]); 8 lanes per (p,k)
    {
        int pk = tid >> 3, sub = tid & 7;
        int p = pk >> 1, k = pk & 1;
        float s = 0.f;
        for (int j = sub; j < 128; j += 8)
            s += Wp[p*128 + j] * Wq[(2*p + k)*128 + j];
        s += __shfl_down_sync(0xffffffffu, s, 4, 8);
        s += __shfl_down_sync(0xffffffffu, s, 2, 8);
        s += __shfl_down_sync(0xffffffffu, s, 1, 8);
        if (sub == 0) scb[pk] = s;
    }
    __syncthreads();
    if (tid < 16) {
        float s0 = scb[2*tid], s1 = scb[2*tid + 1];
        float m = fmaxf(s0, s1);
        float e0 = expf(s0 - m), e1 = expf(s1 - m);
        float inv = 1.f / (e0 + e1);
        scb[2*tid]     = e0 * inv;
        scb[2*tid + 1] = e1 * inv;
    }
    __syncthreads();
    for (int idx = tid; idx < 16*128; idx += NTHREADS) {
        int p = idx / 128, c = idx % 128;
        outb[idx] = feat[(p*3 + 2)*128 + c]
                  + scb[2*p]     * Wq[(2*p)*128 + c]
                  + scb[2*p + 1] * Wq[(2*p + 1)*128 + c];
    }
    __syncthreads();

    float* hb = sm + HB_OFF;
    float* sf = sm + SF_OFF;
    gemm_tile<16,64,128,64,1,4,true,64>(g_WT_m1, att_m1_b, outb, 128, hb, 64, Ws, tid);
    gemm_tile<16,64,64,64,1,4,false,64>(g_WT_m2, att_m2_b, hb, 64, sf, 64, Ws, tid);

    // ============ Phase 5: MLP tail ==========================================
    float* xb  = sm + XB_OFF;
    float* h1b = sm + H1_OFF;
    float* h2b = sm + H2_OFF;
    for (int idx = tid; idx < 16*76; idx += NTHREADS) {
        int p = idx / 76, c = idx % 76;
        float v;
        if (c < 64) v = sf[p*64 + c];
        else        v = (__ldg(&cat_feat[g0 + p]) == (c - 64)) ? 1.f : 0.f;
        xb[idx] = v;
    }
    __syncthreads();
    for (int idx = tid; idx < 16*76; idx += NTHREADS) {
        int p = idx / 76, c = idx % 76;
        const float* w = mlp_w1 + c*76;
        const float* x = xb + p*76;
        float s = mlp_b1[c];
#pragma unroll 4
        for (int k = 0; k < 76; k++) s += x[k] * __ldg(&w[k]);
        h1b[idx] = fmaxf(s, 0.f);
    }
    __syncthreads();
    for (int idx = tid; idx < 16*64; idx += NTHREADS) {
        int p = idx / 64, c = idx % 64;
        const float* w = mlp_w2 + c*76;
        const float* x = h1b + p*76;
        float s = mlp_b2[c];
#pragma unroll 4
        for (int k = 0; k < 76; k++) s += x[k] * __ldg(&w[k]);
        h2b[idx] = fmaxf(s, 0.f);
    }
    __syncthreads();
    if (tid < 16) {
        float z = mlp_b3[0];
        const float* x = h2b + tid*64;
#pragma unroll 4
        for (int k = 0; k < 64; k++) z += x[k] * __ldg(&mlp_w3[k]);
        out[g0 + tid] = 1.f / (1.f + expf(-z));
    }
}

// ---------------------------------------------------------------------------
// Launch
// ---------------------------------------------------------------------------
extern "C" void kernel_launch(void* const* d_in, const int* in_sizes, int n_in,
                              void* d_out, int out_size)
{
    const int*   node_idx      = (const int*)  d_in[0];
    const int*   edge_idx      = (const int*)  d_in[1];
    const int*   cat_feat      = (const int*)  d_in[2];
    const float* t_records     = (const float*)d_in[3];
    const float* edge_identify = (const float*)d_in[4];
    // d_in[5] = cut_time_l (unused by reference)
    const float* node_embed    = (const float*)d_in[6];
    const float* edge_embed    = (const float*)d_in[7];
    const float* basis_freq    = (const float*)d_in[8];
    const float* phase         = (const float*)d_in[9];
    const float* lin_event_w   = (const float*)d_in[10];
    const float* lin_event_b   = (const float*)d_in[11];
    const float* gcn_w1        = (const float*)d_in[12];
    const float* gcn_b1        = (const float*)d_in[13];
    const float* gcn_w2        = (const float*)d_in[14];
    const float* gcn_b2        = (const float*)d_in[15];
    const float* att_w1_w      = (const float*)d_in[16];
    const float* att_w1_b      = (const float*)d_in[17];
    const float* att_w2_w      = (const float*)d_in[18];
    const float* att_w2_b      = (const float*)d_in[19];
    const float* att_m1_w      = (const float*)d_in[20];
    const float* att_m1_b      = (const float*)d_in[21];
    const float* att_m2_w      = (const float*)d_in[22];
    const float* att_m2_b      = (const float*)d_in[23];
    const float* mlp_w1        = (const float*)d_in[24];
    const float* mlp_b1        = (const float*)d_in[25];
    const float* mlp_w2        = (const float*)d_in[26];
    const float* mlp_b2        = (const float*)d_in[27];
    const float* mlp_w3        = (const float*)d_in[28];
    const float* mlp_b3        = (const float*)d_in[29];
    float* outp = (float*)d_out;

    cudaFuncSetAttribute(fused_kernel,
                         cudaFuncAttributeMaxDynamicSharedMemorySize, SMEM_BYTES);

    prep_kernel<<<128, 256>>>(lin_event_w, gcn_w1, gcn_w2,
                              att_w1_w, att_w2_w, att_m1_w, att_m2_w);

    fused_kernel<<<NBLK, NTHREADS, SMEM_BYTES>>>(
        node_idx, edge_idx, cat_feat, t_records, edge_identify,
        node_embed, edge_embed, basis_freq, phase,
        lin_event_b, gcn_b1, gcn_b2,
        att_w1_b, att_w2_b, att_m1_b, att_m2_b,
        mlp_w1, mlp_b1, mlp_w2, mlp_b2, mlp_w3, mlp_b3,
        outp);
}

// round 3
// speedup vs baseline: 1.7472x; 1.3979x over previous
#include <cuda_runtime.h>
#include <math.h>

#define NTHREADS 256
#define PAIRS    16
#define ROWS     48
#define NBLK     2048

typedef unsigned long long ull;

// ---------------------------------------------------------------------------
// smem layout (floats): total 16704 floats = 66816 B -> 3 blocks/SM
// ---------------------------------------------------------------------------
#define EVT_OFF   0        // 48*176 = 8448
#define FEAT_OFF  8448     // 48*128 = 6144
#define ABUF_OFF  14592    // 48*44  = 2112
#define SMEM_FLOATS 16704
#define SMEM_BYTES (SMEM_FLOATS*4)
// aliases inside EVT region (evt dead after gine pass 2 consumes it)
#define TGTB_OFF  0        // 32x128
#define WQ_OFF    4096     // 32x128
#define WP_OFF    0        // 16x128
#define OUTB_OFF  2048     // 16x128
#define SC_OFF    8320     // 32 floats
// aliases inside FEAT region for the tail (feat dead after outb built)
#define HB_OFF    (FEAT_OFF + 0)     // 16x64
#define SF_OFF    (FEAT_OFF + 1024)  // 16x64
#define XB_OFF    (FEAT_OFF + 2048)  // 16x76
#define H1_OFF    (FEAT_OFF + 3328)  // 16x76
#define H2_OFF    (FEAT_OFF + 4608)  // 16x64

// ---------------------------------------------------------------------------
// f32x2 packed-FMA helpers (sm_100+)
// ---------------------------------------------------------------------------
__device__ __forceinline__ ull pack2(float lo, float hi) {
    ull r; asm("mov.b64 %0, {%1, %2};" : "=l"(r) : "f"(lo), "f"(hi)); return r;
}
__device__ __forceinline__ void unpack2(ull v, float& lo, float& hi) {
    asm("mov.b64 {%0, %1}, %2;" : "=f"(lo), "=f"(hi) : "l"(v));
}
__device__ __forceinline__ void fma2(ull& d, ull a, ull b) {
    asm("fma.rn.f32x2 %0, %1, %2, %0;" : "+l"(d) : "l"(a), "l"(b));
}

// ---------------------------------------------------------------------------
// Pre-transposed / padded weights ([k][o] layout, zero padded)
// ---------------------------------------------------------------------------
__device__ __align__(16) float g_WT_event[352*192];
__device__ __align__(16) float g_WT_gcn1 [176*64];
__device__ __align__(16) float g_WT_gcn2 [ 64*64];
__device__ __align__(16) float g_WT_att1 [128*128];
__device__ __align__(16) float g_WT_att2 [128*128];
__device__ __align__(16) float g_WT_m1   [128*64];
__device__ __align__(16) float g_WT_m2   [ 64*64];

__global__ void prep_kernel(const float* __restrict__ ew,
                            const float* __restrict__ g1,
                            const float* __restrict__ g2,
                            const float* __restrict__ a1,
                            const float* __restrict__ a2,
                            const float* __restrict__ m1,
                            const float* __restrict__ m2)
{
    int t0 = blockIdx.x*blockDim.x + threadIdx.x;
    int stride = gridDim.x*blockDim.x;
    for (int i = t0; i < 352*192; i += stride) {
        int k = i/192, o = i%192;
        g_WT_event[i] = (k < 347 && o < 172) ? ew[o*347 + k] : 0.f;
    }
    for (int i = t0; i < 176*64; i += stride) {
        int k = i/64, o = i%64;
        g_WT_gcn1[i] = (k < 172) ? g1[o*172 + k] : 0.f;
    }
    for (int i = t0; i < 64*64; i += stride) {
        int k = i/64, o = i%64;
        g_WT_gcn2[i] = g2[o*64 + k];
        g_WT_m2[i]   = m2[o*64 + k];
    }
    for (int i = t0; i < 128*128; i += stride) {
        int k = i/128, o = i%128;
        g_WT_att1[i] = a1[o*128 + k];
        g_WT_att2[i] = a2[o*128 + k];
    }
    for (int i = t0; i < 128*64; i += stride) {
        int k = i/64, o = i%64;
        g_WT_m1[i] = m1[o*128 + k];
    }
}

// ---------------------------------------------------------------------------
// GEMM cores. Thread grid: 8 warps (ty = tid>>5), 32 lanes (tx).
// Thread (ty,tx) computes rows [ty*RT, ty*RT+RT) and column pairs
// {g*64 + 2*tx, +1} for g in [0,P). Weights read directly from global
// (coalesced LDG.64: warp covers 64 consecutive floats per (k,g)).
// A lives in smem, row pitch sa (multiple of 4 floats, 16B-aligned base).
// ---------------------------------------------------------------------------
template<int N, int K, int RT, int P, bool RELU>
__device__ __forceinline__ void gemm_direct(
    const float* __restrict__ Wg, const float* __restrict__ bias,
    const float* __restrict__ A, int sa,
    float* __restrict__ C, int sc, int tid)
{
    const int ty = tid >> 5, tx = tid & 31;
    ull acc[RT][P];
#pragma unroll
    for (int i = 0; i < RT; i++)
#pragma unroll
        for (int g = 0; g < P; g++) acc[i][g] = 0ull;

    const float* wq   = Wg + 2*tx;
    const float* arow = A + ty*RT*sa;

    for (int k4 = 0; k4 < K; k4 += 4) {
        float4 av[RT];
#pragma unroll
        for (int i = 0; i < RT; i++)
            av[i] = *reinterpret_cast<const float4*>(arow + i*sa + k4);
#pragma unroll
        for (int kk = 0; kk < 4; kk++) {
            ull w[P];
#pragma unroll
            for (int g = 0; g < P; g++)
                w[g] = __ldg(reinterpret_cast<const ull*>(wq + (k4+kk)*N + g*64));
#pragma unroll
            for (int i = 0; i < RT; i++) {
                float a = (kk==0)?av[i].x:(kk==1)?av[i].y:(kk==2)?av[i].z:av[i].w;
                ull ad = pack2(a, a);
#pragma unroll
                for (int g = 0; g < P; g++) fma2(acc[i][g], ad, w[g]);
            }
        }
    }
#pragma unroll
    for (int i = 0; i < RT; i++)
#pragma unroll
        for (int g = 0; g < P; g++) {
            int col = g*64 + 2*tx;
            float x, y; unpack2(acc[i][g], x, y);
            x += __ldg(&bias[col]);
            y += __ldg(&bias[col+1]);
            if (RELU) { x = fmaxf(x, 0.f); y = fmaxf(y, 0.f); }
            C[(ty*RT+i)*sc + col]     = x;
            C[(ty*RT+i)*sc + col + 1] = y;
        }
    __syncthreads();
}

// Chunked variant: A chunk [M][KC] generated into Abuf by functor per chunk.
template<int N, int K, int KC, int RT, int P, bool RELU, int NREAL, typename Gen>
__device__ __forceinline__ void gemm_gen(
    const float* __restrict__ Wg, const float* __restrict__ bias,
    float* __restrict__ Abuf, const Gen& gen,
    float* __restrict__ C, int sc, int tid)
{
    const int ty = tid >> 5, tx = tid & 31;
    ull acc[RT][P];
#pragma unroll
    for (int i = 0; i < RT; i++)
#pragma unroll
        for (int g = 0; g < P; g++) acc[i][g] = 0ull;

#pragma unroll 1
    for (int kc = 0; kc < K; kc += KC) {
        __syncthreads();                 // prior chunk's Abuf reads done
        gen(Abuf, kc, tid);
        __syncthreads();
        const float* wq   = Wg + kc*N + 2*tx;
        const float* arow = Abuf + ty*RT*KC;
        for (int k4 = 0; k4 < KC; k4 += 4) {
            float4 av[RT];
#pragma unroll
            for (int i = 0; i < RT; i++)
                av[i] = *reinterpret_cast<const float4*>(arow + i*KC + k4);
#pragma unroll
            for (int kk = 0; kk < 4; kk++) {
                ull w[P];
#pragma unroll
                for (int g = 0; g < P; g++)
                    w[g] = __ldg(reinterpret_cast<const ull*>(wq + (k4+kk)*N + g*64));
#pragma unroll
                for (int i = 0; i < RT; i++) {
                    float a = (kk==0)?av[i].x:(kk==1)?av[i].y:(kk==2)?av[i].z:av[i].w;
                    ull ad = pack2(a, a);
#pragma unroll
                    for (int g = 0; g < P; g++) fma2(acc[i][g], ad, w[g]);
                }
            }
        }
    }
#pragma unroll
    for (int i = 0; i < RT; i++)
#pragma unroll
        for (int g = 0; g < P; g++) {
            int col = g*64 + 2*tx;
            float x, y; unpack2(acc[i][g], x, y);
            int row = ty*RT + i;
            if (col < NREAL) {
                float v = x + __ldg(&bias[col]);
                if (RELU) v = fmaxf(v, 0.f);
                C[row*sc + col] = v;
            }
            if (col + 1 < NREAL) {
                float v = y + __ldg(&bias[col+1]);
                if (RELU) v = fmaxf(v, 0.f);
                C[row*sc + col + 1] = v;
            }
        }
    __syncthreads();
}

// ---------------------------------------------------------------------------
// A-chunk generators
// ---------------------------------------------------------------------------
struct EventGen {
    const int*   edge_idx;
    const float* edge_embed;
    const float* edge_identify;
    const float* t_records;
    const float* basis_freq;
    const float* phase;
    int g0;
    __device__ __forceinline__ void operator()(float* Abuf, int kc, int tid) const {
        for (int idx = tid; idx < ROWS*44; idx += NTHREADS) {
            int r = idx / 44, cc = idx - r*44;
            int c = kc + cc;
            int p = r / 3, l = r - p*3;
            int g = g0 + p;
            float v = 0.f;
            if (c < 172) {
                int e = __ldg(&edge_idx[g*3 + l]);
                v = __ldg(&edge_embed[(long)e*172 + c]);
            } else if (c < 175) {
                v = __ldg(&edge_identify[(g*3 + l)*3 + (c - 172)]);
            } else if (c < 347) {
                int d = c - 175;
                float dt = __ldg(&t_records[g*3 + 2]) - __ldg(&t_records[g*3 + l]);
                v = __cosf(dt * __ldg(&basis_freq[d]) + __ldg(&phase[d]));
            }
            Abuf[idx] = v;
        }
    }
};

struct GineGen {
    const int*   node_idx;
    const float* node_embed;
    const float* evt;   // smem, pitch 176
    int g0;
    int swap;
    __device__ __forceinline__ void operator()(float* Abuf, int kc, int tid) const {
        for (int idx = tid; idx < ROWS*44; idx += NTHREADS) {
            int r = idx / 44, cc = idx - r*44;
            int c = kc + cc;
            int p = r / 3, l = r - p*3;
            int g = g0 + p;
            float v = 0.f;
            if (c < 172) {
                int ns = __ldg(&node_idx[g*6 + 2*l]);
                int nt = __ldg(&node_idx[g*6 + 2*l + 1]);
                float s = __ldg(&node_embed[(long)ns*172 + c]);
                float t = __ldg(&node_embed[(long)nt*172 + c]);
                float e = evt[r*176 + c];
                v = swap ? (t + fmaxf(s + e, 0.f)) : (s + fmaxf(t + e, 0.f));
            }
            Abuf[idx] = v;
        }
    }
};

// ---------------------------------------------------------------------------
// Fused main kernel: one block handles 16 (b,w) pairs end-to-end.
// ---------------------------------------------------------------------------
__global__ void __launch_bounds__(NTHREADS, 3)
fused_kernel(const int*   __restrict__ node_idx,
             const int*   __restrict__ edge_idx,
             const int*   __restrict__ cat_feat,
             const float* __restrict__ t_records,
             const float* __restrict__ edge_identify,
             const float* __restrict__ node_embed,
             const float* __restrict__ edge_embed,
             const float* __restrict__ basis_freq,
             const float* __restrict__ phase,
             const float* __restrict__ lin_event_b,
             const float* __restrict__ gcn_b1,
             const float* __restrict__ gcn_b2,
             const float* __restrict__ att_w1_b,
             const float* __restrict__ att_w2_b,
             const float* __restrict__ att_m1_b,
             const float* __restrict__ att_m2_b,
             const float* __restrict__ mlp_w1,
             const float* __restrict__ mlp_b1,
             const float* __restrict__ mlp_w2,
             const float* __restrict__ mlp_b2,
             const float* __restrict__ mlp_w3,
             const float* __restrict__ mlp_b3,
             float*       __restrict__ out)
{
    extern __shared__ float sm[];
    const int tid = threadIdx.x;
    const int g0  = blockIdx.x * PAIRS;

    float* evt  = sm + EVT_OFF;
    float* feat = sm + FEAT_OFF;
    float* Abuf = sm + ABUF_OFF;

    // ---- Phase 1: event linear (K padded 352, N padded 192, real 172) ----
    EventGen eg{edge_idx, edge_embed, edge_identify, t_records, basis_freq, phase, g0};
    gemm_gen<192,352,44,6,3,false,172>(g_WT_event, lin_event_b, Abuf, eg, evt, 176, tid);

    // ---- Phase 2: gine(src,tgt) -> feat[:,0:64] ----
    GineGen gg1{node_idx, node_embed, evt, g0, 0};
    gemm_gen<64,176,44,6,1,true,64>(g_WT_gcn1, gcn_b1, Abuf, gg1, feat + 64, 128, tid);
    gemm_direct<64,64,6,1,false>(g_WT_gcn2, gcn_b2, feat + 64, 128, feat + 0, 128, tid);

    // ---- Phase 3: gine(tgt,src) -> feat[:,64:128]  (H lives in evt, dead) --
    GineGen gg2{node_idx, node_embed, evt, g0, 1};
    gemm_gen<64,176,44,6,1,true,64>(g_WT_gcn1, gcn_b1, Abuf, gg2, evt, 64, tid);
    gemm_direct<64,64,6,1,false>(g_WT_gcn2, gcn_b2, evt, 64, feat + 64, 128, tid);

    // ---- Phase 4: attention ----
    float* tgtb = sm + TGTB_OFF;
    for (int idx = tid; idx < 32*128; idx += NTHREADS) {
        int r = idx >> 7, c = idx & 127;
        tgtb[idx] = feat[((r >> 1)*3 + (r & 1))*128 + c];
    }
    __syncthreads();
    float* Wq = sm + WQ_OFF;
    gemm_direct<128,128,4,2,false>(g_WT_att2, att_w2_b, tgtb, 128, Wq, 128, tid);
    float* Wp = sm + WP_OFF;   // overwrites tgtb (dead)
    gemm_direct<128,128,2,2,false>(g_WT_att1, att_w1_b, feat + 256, 384, Wp, 128, tid);

    float* scb = sm + SC_OFF;
    {
        int pk = tid >> 3, sub = tid & 7;   // pk 0..31
        int p = pk >> 1, k = pk & 1;
        float s = 0.f;
        for (int j = sub; j < 128; j += 8)
            s += Wp[p*128 + j] * Wq[(2*p + k)*128 + j];
        s += __shfl_down_sync(0xffffffffu, s, 4, 8);
        s += __shfl_down_sync(0xffffffffu, s, 2, 8);
        s += __shfl_down_sync(0xffffffffu, s, 1, 8);
        if (sub == 0) scb[pk] = s;
    }
    __syncthreads();
    if (tid < 16) {
        float s0 = scb[2*tid], s1 = scb[2*tid + 1];
        float m = fmaxf(s0, s1);
        float e0 = expf(s0 - m), e1 = expf(s1 - m);
        float inv = 1.f / (e0 + e1);
        scb[2*tid]     = e0 * inv;
        scb[2*tid + 1] = e1 * inv;
    }
    __syncthreads();
    float* outb = sm + OUTB_OFF;
    for (int idx = tid; idx < 16*128; idx += NTHREADS) {
        int p = idx >> 7, c = idx & 127;
        outb[idx] = feat[(p*3 + 2)*128 + c]
                  + scb[2*p]     * Wq[(2*p)*128 + c]
                  + scb[2*p + 1] * Wq[(2*p + 1)*128 + c];
    }
    __syncthreads();

    float* hb = sm + HB_OFF;
    float* sf = sm + SF_OFF;
    gemm_direct<64,128,2,1,true>(g_WT_m1, att_m1_b, outb, 128, hb, 64, tid);
    gemm_direct<64,64,2,1,false>(g_WT_m2, att_m2_b, hb, 64, sf, 64, tid);

    // ---- Phase 5: MLP tail ----
    float* xb  = sm + XB_OFF;
    float* h1b = sm + H1_OFF;
    float* h2b = sm + H2_OFF;
    for (int idx = tid; idx < 16*76; idx += NTHREADS) {
        int p = idx / 76, c = idx - p*76;
        float v;
        if (c < 64) v = sf[p*64 + c];
        else        v = (__ldg(&cat_feat[g0 + p]) == (c - 64)) ? 1.f : 0.f;
        xb[idx] = v;
    }
    __syncthreads();
    for (int idx = tid; idx < 16*76; idx += NTHREADS) {
        int p = idx / 76, c = idx - p*76;
        const float* w = mlp_w1 + c*76;
        const float* x = xb + p*76;
        float s = __ldg(&mlp_b1[c]);
#pragma unroll 4
        for (int k = 0; k < 76; k++) s += x[k] * __ldg(&w[k]);
        h1b[idx] = fmaxf(s, 0.f);
    }
    __syncthreads();
    for (int idx = tid; idx < 16*64; idx += NTHREADS) {
        int p = idx >> 6, c = idx & 63;
        const float* w = mlp_w2 + c*76;
        const float* x = h1b + p*76;
        float s = __ldg(&mlp_b2[c]);
#pragma unroll 4
        for (int k = 0; k < 76; k++) s += x[k] * __ldg(&w[k]);
        h2b[idx] = fmaxf(s, 0.f);
    }
    __syncthreads();
    if (tid < 16) {
        float z = __ldg(&mlp_b3[0]);
        const float* x = h2b + tid*64;
#pragma unroll 4
        for (int k = 0; k < 64; k++) z += x[k] * __ldg(&mlp_w3[k]);
        out[g0 + tid] = 1.f / (1.f + expf(-z));
    }
}

// ---------------------------------------------------------------------------
// Launch
// ---------------------------------------------------------------------------
extern "C" void kernel_launch(void* const* d_in, const int* in_sizes, int n_in,
                              void* d_out, int out_size)
{
    const int*   node_idx      = (const int*)  d_in[0];
    const int*   edge_idx      = (const int*)  d_in[1];
    const int*   cat_feat      = (const int*)  d_in[2];
    const float* t_records     = (const float*)d_in[3];
    const float* edge_identify = (const float*)d_in[4];
    // d_in[5] = cut_time_l (unused by reference)
    const float* node_embed    = (const float*)d_in[6];
    const float* edge_embed    = (const float*)d_in[7];
    const float* basis_freq    = (const float*)d_in[8];
    const float* phase         = (const float*)d_in[9];
    const float* lin_event_w   = (const float*)d_in[10];
    const float* lin_event_b   = (const float*)d_in[11];
    const float* gcn_w1        = (const float*)d_in[12];
    const float* gcn_b1        = (const float*)d_in[13];
    const float* gcn_w2        = (const float*)d_in[14];
    const float* gcn_b2        = (const float*)d_in[15];
    const float* att_w1_w      = (const float*)d_in[16];
    const float* att_w1_b      = (const float*)d_in[17];
    const float* att_w2_w      = (const float*)d_in[18];
    const float* att_w2_b      = (const float*)d_in[19];
    const float* att_m1_w      = (const float*)d_in[20];
    const float* att_m1_b      = (const float*)d_in[21];
    const float* att_m2_w      = (const float*)d_in[22];
    const float* att_m2_b      = (const float*)d_in[23];
    const float* mlp_w1        = (const float*)d_in[24];
    const float* mlp_b1        = (const float*)d_in[25];
    const float* mlp_w2        = (const float*)d_in[26];
    const float* mlp_b2        = (const float*)d_in[27];
    const float* mlp_w3        = (const float*)d_in[28];
    const float* mlp_b3        = (const float*)d_in[29];
    float* outp = (float*)d_out;

    cudaFuncSetAttribute(fused_kernel,
                         cudaFuncAttributeMaxDynamicSharedMemorySize, SMEM_BYTES);

    prep_kernel<<<128, 256>>>(lin_event_w, gcn_w1, gcn_w2,
                              att_w1_w, att_w2_w, att_m1_w, att_m2_w);

    fused_kernel<<<NBLK, NTHREADS, SMEM_BYTES>>>(
        node_idx, edge_idx, cat_feat, t_records, edge_identify,
        node_embed, edge_embed, basis_freq, phase,
        lin_event_b, gcn_b1, gcn_b2,
        att_w1_b, att_w2_b, att_m1_b, att_m2_b,
        mlp_w1, mlp_b1, mlp_w2, mlp_b2, mlp_w3, mlp_b3,
        outp);
}